// round 8
// baseline (speedup 1.0000x reference)
#include <cuda_runtime.h>
#include <cuda_bf16.h>
#include <math.h>
#include <stdint.h>

// Problem constants
#define Bc 2
#define Tc 2048
#define Dc 1024
#define Hc 16
#define Lc 8
#define Ic 4096
#define HD 64
#define ROWS (Bc*Tc)    // 4096 token rows
#define LN_EPS 1e-5f
#define MASK_BIAS -10000.0f

typedef __nv_bfloat16 bf16;

// ---------------- scratch (static device globals; no allocation) -------------
__device__ float g_h[ROWS * Dc];            // residual stream (fp32)
__device__ float g_qkv[ROWS * 3 * Dc];      // qkv projection (fp32)
__device__ bf16  g_xhi[ROWS * Dc],  g_xlo[ROWS * Dc];     // LN output split
__device__ bf16  g_chi[ROWS * Dc],  g_clo[ROWS * Dc];     // attention ctx split
__device__ bf16  g_ahi[ROWS * Ic],  g_alo[ROWS * Ic];     // ffn inner split
// weight splits [K, N] layout (same as source)
__device__ bf16 g_wqkv_hi[Lc*Dc*3*Dc], g_wqkv_lo[Lc*Dc*3*Dc];
__device__ bf16 g_wprj_hi[Lc*Dc*Dc],   g_wprj_lo[Lc*Dc*Dc];
__device__ bf16 g_wfc_hi [Lc*Dc*Ic],   g_wfc_lo [Lc*Dc*Ic];
__device__ bf16 g_wfp_hi [Lc*Ic*Dc],   g_wfp_lo [Lc*Ic*Dc];

// ---------------- utility ----------------------------------------------------
__inline__ __device__ float warp_sum(float v) {
    #pragma unroll
    for (int o = 16; o > 0; o >>= 1) v += __shfl_xor_sync(0xffffffffu, v, o);
    return v;
}
__device__ __forceinline__ void split2(float v, bf16& hi, bf16& lo) {
    hi = __float2bfloat16(v);
    lo = __float2bfloat16(v - __bfloat162float(hi));
}

// ---------------- copy / weight split ----------------------------------------
__global__ void copy_kernel(const float* __restrict__ src, float* __restrict__ dst, int n) {
    int i = blockIdx.x * blockDim.x + threadIdx.x;
    if (i < n) dst[i] = src[i];
}

__global__ void split4_kernel(const float* __restrict__ src,
                              bf16* __restrict__ hi, bf16* __restrict__ lo, int n4) {
    int i = blockIdx.x * blockDim.x + threadIdx.x;
    if (i >= n4) return;
    float4 v = ((const float4*)src)[i];
    bf16 h0,l0,h1,l1,h2,l2,h3,l3;
    split2(v.x,h0,l0); split2(v.y,h1,l1); split2(v.z,h2,l2); split2(v.w,h3,l3);
    __nv_bfloat162* H = (__nv_bfloat162*)(hi + 4*(size_t)i);
    __nv_bfloat162* L = (__nv_bfloat162*)(lo + 4*(size_t)i);
    H[0] = __nv_bfloat162(h0,h1); H[1] = __nv_bfloat162(h2,h3);
    L[0] = __nv_bfloat162(l0,l1); L[1] = __nv_bfloat162(l2,l3);
}

// ---------------- layernorm (optionally writing hi/lo bf16 split) ------------
template<bool SPLIT>
__global__ __launch_bounds__(256) void ln_kernel(
    const float* __restrict__ in, const float* __restrict__ w,
    const float* __restrict__ b, float* __restrict__ outf,
    bf16* __restrict__ outhi, bf16* __restrict__ outlo)
{
    int row = blockIdx.x;
    const float* x = in + (size_t)row * Dc;
    float s = 0.f, s2 = 0.f;
    for (int i = threadIdx.x; i < Dc; i += 256) {
        float v = x[i]; s += v; s2 += v * v;
    }
    __shared__ float r1[8], r2[8];
    s = warp_sum(s); s2 = warp_sum(s2);
    int wid = threadIdx.x >> 5, lane = threadIdx.x & 31;
    if (lane == 0) { r1[wid] = s; r2[wid] = s2; }
    __syncthreads();
    if (wid == 0) {
        s  = (lane < 8) ? r1[lane] : 0.f;
        s2 = (lane < 8) ? r2[lane] : 0.f;
        s = warp_sum(s); s2 = warp_sum(s2);
        if (lane == 0) { r1[0] = s; r2[0] = s2; }
    }
    __syncthreads();
    float mean = r1[0] * (1.0f / Dc);
    float var  = r2[0] * (1.0f / Dc) - mean * mean;
    float inv  = rsqrtf(var + LN_EPS);
    for (int i = threadIdx.x; i < Dc; i += 256) {
        float v = (x[i] - mean) * inv * w[i] + b[i];
        if (SPLIT) {
            bf16 hh, ll; split2(v, hh, ll);
            outhi[(size_t)row * Dc + i] = hh;
            outlo[(size_t)row * Dc + i] = ll;
        } else {
            outf[(size_t)row * Dc + i] = v;
        }
    }
}

// ---------------- tensor-core GEMM (bf16x3 emulation of fp32) -----------------
// C[M,N] = A[M,K] @ W[K,N] + bias  via  Ahi*Whi + Ahi*Wlo + Alo*Whi (HMMA)
// EPI 0: Cf = v ;  EPI 1: Cf = res + v ;  EPI 2: relu(v) -> (Chi, Clo) split
#define GBM 128
#define GBN 128
#define GBK 32
#define APAD 8
#define BPAD 8
#define ASTRIDE (GBK + APAD)     // 40
#define BSTRIDE (GBN + BPAD)     // 136
#define SA_ELEMS (2*2*GBM*ASTRIDE)
#define SB_ELEMS (2*2*GBK*BSTRIDE)
#define GSMEM_BYTES ((SA_ELEMS + SB_ELEMS) * 2)

__device__ __forceinline__ void ldsm4(unsigned* r, unsigned addr) {
    asm volatile("ldmatrix.sync.aligned.m8n8.x4.shared.b16 {%0,%1,%2,%3},[%4];"
        : "=r"(r[0]), "=r"(r[1]), "=r"(r[2]), "=r"(r[3]) : "r"(addr));
}
__device__ __forceinline__ void ldsm4t(unsigned* r, unsigned addr) {
    asm volatile("ldmatrix.sync.aligned.m8n8.x4.trans.shared.b16 {%0,%1,%2,%3},[%4];"
        : "=r"(r[0]), "=r"(r[1]), "=r"(r[2]), "=r"(r[3]) : "r"(addr));
}
__device__ __forceinline__ void mma16816(float* c, const unsigned* a, const unsigned* b) {
    asm volatile("mma.sync.aligned.m16n8k16.row.col.f32.bf16.bf16.f32 "
        "{%0,%1,%2,%3},{%4,%5,%6,%7},{%8,%9},{%0,%1,%2,%3};"
        : "+f"(c[0]), "+f"(c[1]), "+f"(c[2]), "+f"(c[3])
        : "r"(a[0]), "r"(a[1]), "r"(a[2]), "r"(a[3]), "r"(b[0]), "r"(b[1]));
}
__device__ __forceinline__ void cp_async16(unsigned saddr, const void* g) {
    asm volatile("cp.async.cg.shared.global [%0], [%1], 16;" :: "r"(saddr), "l"(g));
}

template<int EPI>
__global__ void __launch_bounds__(512) gemm3_kernel(
    const bf16* __restrict__ Ahi, const bf16* __restrict__ Alo,
    const bf16* __restrict__ Bhi, const bf16* __restrict__ Blo,
    const float* __restrict__ bias, const float* __restrict__ res,
    float* __restrict__ Cf, bf16* __restrict__ Chi, bf16* __restrict__ Clo,
    int M, int N, int K)
{
    extern __shared__ __align__(16) bf16 smem[];
    bf16* sA = smem;               // [buf][p][128][ASTRIDE]
    bf16* sB = smem + SA_ELEMS;    // [buf][p][32][BSTRIDE]
    const int tid = threadIdx.x;
    const int lane = tid & 31, wid = tid >> 5;
    const int wm = wid & 3, wn = wid >> 2;   // 4x4 warp grid, 32x32 tiles
    const int bm = blockIdx.y * GBM, bn = blockIdx.x * GBN;

    unsigned sA_base = (unsigned)__cvta_generic_to_shared(sA);
    unsigned sB_base = (unsigned)__cvta_generic_to_shared(sB);

    float acc[2][4][4] = {};

    auto issue = [&](int it, int buf) {
        int k0 = it * GBK;
        #pragma unroll
        for (int j = 0; j < 2; j++) {           // A: 1024 16B chunks total
            int c = tid + j * 512;
            int p = c >> 9, rem = c & 511;
            int r = rem >> 2, kc = (rem & 3) << 3;
            const bf16* src = (p ? Alo : Ahi) + (size_t)(bm + r) * K + k0 + kc;
            unsigned dst = sA_base + (unsigned)(((buf*2 + p)*GBM + r)*ASTRIDE + kc) * 2u;
            cp_async16(dst, src);
        }
        #pragma unroll
        for (int j = 0; j < 2; j++) {           // B: 1024 16B chunks total
            int c = tid + j * 512;
            int p = c >> 9, rem = c & 511;
            int k = rem >> 4, nc = (rem & 15) << 3;
            const bf16* src = (p ? Blo : Bhi) + (size_t)(k0 + k) * N + bn + nc;
            unsigned dst = sB_base + (unsigned)(((buf*2 + p)*GBK + k)*BSTRIDE + nc) * 2u;
            cp_async16(dst, src);
        }
        asm volatile("cp.async.commit_group;" ::: "memory");
    };

    issue(0, 0);
    const int NIT = K >> 5;
    for (int it = 0; it < NIT; it++) {
        int buf = it & 1;
        if (it + 1 < NIT) {
            issue(it + 1, buf ^ 1);
            asm volatile("cp.async.wait_group 1;" ::: "memory");
        } else {
            asm volatile("cp.async.wait_group 0;" ::: "memory");
        }
        __syncthreads();
        #pragma unroll
        for (int ks = 0; ks < 2; ks++) {
            unsigned afrag[2][2][4];   // [mt][p]
            unsigned bfrag[2][4][2];   // [p][nt]
            int arow = wm * 32 + (lane & 15);
            int acol = ks * 16 + ((lane >> 4) << 3);
            #pragma unroll
            for (int mt = 0; mt < 2; mt++)
                #pragma unroll
                for (int p = 0; p < 2; p++)
                    ldsm4(afrag[mt][p],
                          sA_base + (unsigned)(((buf*2 + p)*GBM + arow + mt*16)*ASTRIDE + acol) * 2u);
            int brow = ks * 16 + (lane & 15);
            #pragma unroll
            for (int ng = 0; ng < 2; ng++) {
                int bcol = wn * 32 + ng * 16 + ((lane >> 4) << 3);
                #pragma unroll
                for (int p = 0; p < 2; p++) {
                    unsigned r4[4];
                    ldsm4t(r4, sB_base + (unsigned)(((buf*2 + p)*GBK + brow)*BSTRIDE + bcol) * 2u);
                    bfrag[p][2*ng][0]   = r4[0]; bfrag[p][2*ng][1]   = r4[1];
                    bfrag[p][2*ng+1][0] = r4[2]; bfrag[p][2*ng+1][1] = r4[3];
                }
            }
            // term-outer ordering: same-accumulator reuse distance = 8 MMAs
            #pragma unroll
            for (int mt = 0; mt < 2; mt++)
                #pragma unroll
                for (int nt = 0; nt < 4; nt++)
                    mma16816(acc[mt][nt], afrag[mt][0], bfrag[0][nt]);   // hi*hi
            #pragma unroll
            for (int mt = 0; mt < 2; mt++)
                #pragma unroll
                for (int nt = 0; nt < 4; nt++)
                    mma16816(acc[mt][nt], afrag[mt][0], bfrag[1][nt]);   // hi*lo
            #pragma unroll
            for (int mt = 0; mt < 2; mt++)
                #pragma unroll
                for (int nt = 0; nt < 4; nt++)
                    mma16816(acc[mt][nt], afrag[mt][1], bfrag[0][nt]);   // lo*hi
        }
        __syncthreads();
    }

    // epilogue
    #pragma unroll
    for (int mt = 0; mt < 2; mt++) {
        #pragma unroll
        for (int nt = 0; nt < 4; nt++) {
            int r0 = bm + wm * 32 + mt * 16 + (lane >> 2);
            int c0 = bn + wn * 32 + nt * 8 + ((lane & 3) << 1);
            #pragma unroll
            for (int hh = 0; hh < 2; hh++) {
                int rr = r0 + hh * 8;
                #pragma unroll
                for (int cc = 0; cc < 2; cc++) {
                    int col = c0 + cc;
                    float v = acc[mt][nt][hh*2 + cc] + bias[col];
                    size_t idx = (size_t)rr * N + col;
                    if (EPI == 0) {
                        Cf[idx] = v;
                    } else if (EPI == 1) {
                        Cf[idx] = res[idx] + v;
                    } else {
                        v = fmaxf(v, 0.f);
                        bf16 vh, vl; split2(v, vh, vl);
                        Chi[idx] = vh; Clo[idx] = vl;
                    }
                }
            }
        }
    }
}

// ---------------- fused causal attention (flash-lite) ------------------------
#define BQ 32
#define BKT 32
__global__ __launch_bounds__(256) void attn_kernel(
    const float* __restrict__ qkv, const float* __restrict__ amask,
    bf16* __restrict__ ctxhi, bf16* __restrict__ ctxlo)
{
    __shared__ __align__(16) float Qs[BQ][HD];
    __shared__ __align__(16) float Ks[BKT][HD];
    __shared__ __align__(16) float Vs[BKT][HD];
    __shared__ float Ss[BQ][BKT];
    __shared__ float mrow[BQ], lrow[BQ], crow[BQ];

    int tid = threadIdx.x;
    int bh = blockIdx.y;
    int b = bh / Hc, hh = bh % Hc;
    int q0 = blockIdx.x * BQ;

    const float* qbase = qkv + (size_t)b * Tc * 3 * Dc + hh * HD;
    const float* kbase = qbase + Dc;
    const float* vbase = qbase + 2 * Dc;

    for (int i = tid; i < BQ * HD; i += 256) {
        int r = i >> 6, d = i & 63;
        Qs[r][d] = qbase[(size_t)(q0 + r) * 3 * Dc + d];
    }
    if (tid < BQ) { mrow[tid] = -1e30f; lrow[tid] = 0.f; }

    int tq = tid >> 3;
    int dbase = (tid & 7) << 3;
    float acc[8] = {};
    const float scale = 0.125f;

    int ntiles = blockIdx.x + 1;
    for (int kt = 0; kt < ntiles; kt++) {
        int kk0 = kt * BKT;
        __syncthreads();
        for (int i = tid; i < BKT * HD; i += 256) {
            int r = i >> 6, d = i & 63;
            Ks[r][d] = kbase[(size_t)(kk0 + r) * 3 * Dc + d];
            Vs[r][d] = vbase[(size_t)(kk0 + r) * 3 * Dc + d];
        }
        __syncthreads();
        {
            int sq = tid >> 3;
            int c0 = (tid & 7) << 2;
            float sv[4] = {0.f, 0.f, 0.f, 0.f};
            #pragma unroll
            for (int d = 0; d < HD; d++) {
                float qv = Qs[sq][d];
                sv[0] += qv * Ks[c0 + 0][d];
                sv[1] += qv * Ks[c0 + 1][d];
                sv[2] += qv * Ks[c0 + 2][d];
                sv[3] += qv * Ks[c0 + 3][d];
            }
            int qg = q0 + sq;
            #pragma unroll
            for (int j = 0; j < 4; j++) {
                int kg = kk0 + c0 + j;
                float s;
                if (kg <= qg)
                    s = sv[j] * scale + (1.0f - amask[b * Tc + kg]) * MASK_BIAS;
                else
                    s = -1e30f;
                Ss[sq][c0 + j] = s;
            }
        }
        __syncthreads();
        if (tid < BQ) {
            float m = mrow[tid];
            float tm = m;
            #pragma unroll
            for (int j = 0; j < BKT; j++) tm = fmaxf(tm, Ss[tid][j]);
            float corr = __expf(m - tm);
            float l = lrow[tid] * corr;
            #pragma unroll
            for (int j = 0; j < BKT; j++) {
                float p = __expf(Ss[tid][j] - tm);
                Ss[tid][j] = p;
                l += p;
            }
            mrow[tid] = tm; lrow[tid] = l; crow[tid] = corr;
        }
        __syncthreads();
        float corr = crow[tq];
        #pragma unroll
        for (int j = 0; j < 8; j++) acc[j] *= corr;
        #pragma unroll 4
        for (int kkk = 0; kkk < BKT; kkk++) {
            float p = Ss[tq][kkk];
            float4 v0 = *(const float4*)&Vs[kkk][dbase];
            float4 v1 = *(const float4*)&Vs[kkk][dbase + 4];
            acc[0] += p * v0.x; acc[1] += p * v0.y;
            acc[2] += p * v0.z; acc[3] += p * v0.w;
            acc[4] += p * v1.x; acc[5] += p * v1.y;
            acc[6] += p * v1.z; acc[7] += p * v1.w;
        }
    }
    __syncthreads();
    float linv = 1.0f / lrow[tq];
    size_t obase = ((size_t)(b * Tc + q0 + tq)) * Dc + hh * HD + dbase;
    #pragma unroll
    for (int j = 0; j < 8; j++) {
        float v = acc[j] * linv;
        bf16 vh, vl; split2(v, vh, vl);
        ctxhi[obase + j] = vh;
        ctxlo[obase + j] = vl;
    }
}

// ---------------- launch -----------------------------------------------------
extern "C" void kernel_launch(void* const* d_in, const int* in_sizes, int n_in,
                              void* d_out, int out_size)
{
    const float* emb    = (const float*)d_in[0];
    const float* amask  = (const float*)d_in[1];
    const float* ln1_w  = (const float*)d_in[2];
    const float* ln1_b  = (const float*)d_in[3];
    const float* attn_w = (const float*)d_in[4];
    const float* attn_b = (const float*)d_in[5];
    const float* proj_w = (const float*)d_in[6];
    const float* proj_b = (const float*)d_in[7];
    const float* ln2_w  = (const float*)d_in[8];
    const float* ln2_b  = (const float*)d_in[9];
    const float* fc_w   = (const float*)d_in[10];
    const float* fc_b   = (const float*)d_in[11];
    const float* fcp_w  = (const float*)d_in[12];
    const float* fcp_b  = (const float*)d_in[13];
    const float* lnf_w  = (const float*)d_in[14];
    const float* lnf_b  = (const float*)d_in[15];
    float* out = (float*)d_out;

    float *h, *qkvb;
    bf16 *xhi, *xlo, *chi, *clo, *ahi, *alo;
    bf16 *wq_h, *wq_l, *wp_h, *wp_l, *wf_h, *wf_l, *wg_h, *wg_l;
    cudaGetSymbolAddress((void**)&h,    g_h);
    cudaGetSymbolAddress((void**)&qkvb, g_qkv);
    cudaGetSymbolAddress((void**)&xhi,  g_xhi);  cudaGetSymbolAddress((void**)&xlo, g_xlo);
    cudaGetSymbolAddress((void**)&chi,  g_chi);  cudaGetSymbolAddress((void**)&clo, g_clo);
    cudaGetSymbolAddress((void**)&ahi,  g_ahi);  cudaGetSymbolAddress((void**)&alo, g_alo);
    cudaGetSymbolAddress((void**)&wq_h, g_wqkv_hi); cudaGetSymbolAddress((void**)&wq_l, g_wqkv_lo);
    cudaGetSymbolAddress((void**)&wp_h, g_wprj_hi); cudaGetSymbolAddress((void**)&wp_l, g_wprj_lo);
    cudaGetSymbolAddress((void**)&wf_h, g_wfc_hi);  cudaGetSymbolAddress((void**)&wf_l, g_wfc_lo);
    cudaGetSymbolAddress((void**)&wg_h, g_wfp_hi);  cudaGetSymbolAddress((void**)&wg_l, g_wfp_lo);

    cudaFuncSetAttribute(gemm3_kernel<0>, cudaFuncAttributeMaxDynamicSharedMemorySize, GSMEM_BYTES);
    cudaFuncSetAttribute(gemm3_kernel<1>, cudaFuncAttributeMaxDynamicSharedMemorySize, GSMEM_BYTES);
    cudaFuncSetAttribute(gemm3_kernel<2>, cudaFuncAttributeMaxDynamicSharedMemorySize, GSMEM_BYTES);

    // weight splits [K,N] hi/lo
    { int n4 = Lc*Dc*3*Dc/4; split4_kernel<<<(n4+255)/256, 256>>>(attn_w, wq_h, wq_l, n4); }
    { int n4 = Lc*Dc*Dc/4;   split4_kernel<<<(n4+255)/256, 256>>>(proj_w, wp_h, wp_l, n4); }
    { int n4 = Lc*Dc*Ic/4;   split4_kernel<<<(n4+255)/256, 256>>>(fc_w,   wf_h, wf_l, n4); }
    { int n4 = Lc*Ic*Dc/4;   split4_kernel<<<(n4+255)/256, 256>>>(fcp_w,  wg_h, wg_l, n4); }

    // h = inputs_embeds
    { int n = ROWS * Dc; copy_kernel<<<(n + 255) / 256, 256>>>(emb, h, n); }

    for (int l = 0; l < Lc; l++) {
        // x = ln1(h) -> split
        ln_kernel<true><<<ROWS, 256>>>(h, ln1_w + (size_t)l*Dc, ln1_b + (size_t)l*Dc,
                                       nullptr, xhi, xlo);
        // qkv = x @ attn_w + attn_b  (fp32 out)
        gemm3_kernel<0><<<dim3(3*Dc/GBN, ROWS/GBM), 512, GSMEM_BYTES>>>(
            xhi, xlo, wq_h + (size_t)l*Dc*3*Dc, wq_l + (size_t)l*Dc*3*Dc,
            attn_b + (size_t)l*3*Dc, nullptr, qkvb, nullptr, nullptr,
            ROWS, 3*Dc, Dc);
        // ctx = attention(qkv) -> split
        attn_kernel<<<dim3(Tc/BQ, Bc*Hc), 256>>>(qkvb, amask, chi, clo);
        // h = h + ctx @ proj_w + proj_b
        gemm3_kernel<1><<<dim3(Dc/GBN, ROWS/GBM), 512, GSMEM_BYTES>>>(
            chi, clo, wp_h + (size_t)l*Dc*Dc, wp_l + (size_t)l*Dc*Dc,
            proj_b + (size_t)l*Dc, h, h, nullptr, nullptr,
            ROWS, Dc, Dc);
        // x = ln2(h) -> split
        ln_kernel<true><<<ROWS, 256>>>(h, ln2_w + (size_t)l*Dc, ln2_b + (size_t)l*Dc,
                                       nullptr, xhi, xlo);
        // act = relu(x @ fc_w + fc_b) -> split
        gemm3_kernel<2><<<dim3(Ic/GBN, ROWS/GBM), 512, GSMEM_BYTES>>>(
            xhi, xlo, wf_h + (size_t)l*Dc*Ic, wf_l + (size_t)l*Dc*Ic,
            fc_b + (size_t)l*Ic, nullptr, nullptr, ahi, alo,
            ROWS, Ic, Dc);
        // h = h + act @ fcp_w + fcp_b
        gemm3_kernel<1><<<dim3(Dc/GBN, ROWS/GBM), 512, GSMEM_BYTES>>>(
            ahi, alo, wg_h + (size_t)l*Ic*Dc, wg_l + (size_t)l*Ic*Dc,
            fcp_b + (size_t)l*Dc, h, h, nullptr, nullptr,
            ROWS, Dc, Ic);
    }
    // out = ln_f(h) (fp32)
    ln_kernel<false><<<ROWS, 256>>>(h, lnf_w, lnf_b, out, nullptr, nullptr);
}

// round 9
// speedup vs baseline: 5.4871x; 5.4871x over previous
#include <cuda_runtime.h>
#include <cuda_bf16.h>
#include <math.h>
#include <stdint.h>

// Problem constants
#define Bc 2
#define Tc 2048
#define Dc 1024
#define Hc 16
#define Lc 8
#define Ic 4096
#define HD 64
#define ROWS (Bc*Tc)    // 4096 token rows
#define LN_EPS 1e-5f
#define MASK_BIAS -10000.0f

typedef __nv_bfloat16 bf16;

// ---------------- scratch (static device globals; no allocation) -------------
__device__ float g_h[ROWS * Dc];            // residual stream (fp32)
__device__ bf16  g_qhi[ROWS * 3 * Dc], g_qlo[ROWS * 3 * Dc];  // qkv split
__device__ bf16  g_xhi[ROWS * Dc],  g_xlo[ROWS * Dc];     // LN output split
__device__ bf16  g_chi[ROWS * Dc],  g_clo[ROWS * Dc];     // attention ctx split
__device__ bf16  g_ahi[ROWS * Ic],  g_alo[ROWS * Ic];     // ffn inner split
// weight splits [K, N] layout
__device__ bf16 g_wqkv_hi[Lc*Dc*3*Dc], g_wqkv_lo[Lc*Dc*3*Dc];
__device__ bf16 g_wprj_hi[Lc*Dc*Dc],   g_wprj_lo[Lc*Dc*Dc];
__device__ bf16 g_wfc_hi [Lc*Dc*Ic],   g_wfc_lo [Lc*Dc*Ic];
__device__ bf16 g_wfp_hi [Lc*Ic*Dc],   g_wfp_lo [Lc*Ic*Dc];

// ---------------- utility ----------------------------------------------------
__inline__ __device__ float warp_sum(float v) {
    #pragma unroll
    for (int o = 16; o > 0; o >>= 1) v += __shfl_xor_sync(0xffffffffu, v, o);
    return v;
}
__device__ __forceinline__ void split2(float v, bf16& hi, bf16& lo) {
    hi = __float2bfloat16(v);
    lo = __float2bfloat16(v - __bfloat162float(hi));
}

// ---------------- copy / weight split ----------------------------------------
__global__ void copy_kernel(const float* __restrict__ src, float* __restrict__ dst, int n) {
    int i = blockIdx.x * blockDim.x + threadIdx.x;
    if (i < n) dst[i] = src[i];
}

__global__ void split4_kernel(const float* __restrict__ src,
                              bf16* __restrict__ hi, bf16* __restrict__ lo, int n4) {
    int i = blockIdx.x * blockDim.x + threadIdx.x;
    if (i >= n4) return;
    float4 v = ((const float4*)src)[i];
    bf16 h0,l0,h1,l1,h2,l2,h3,l3;
    split2(v.x,h0,l0); split2(v.y,h1,l1); split2(v.z,h2,l2); split2(v.w,h3,l3);
    __nv_bfloat162* H = (__nv_bfloat162*)(hi + 4*(size_t)i);
    __nv_bfloat162* L = (__nv_bfloat162*)(lo + 4*(size_t)i);
    H[0] = __nv_bfloat162(h0,h1); H[1] = __nv_bfloat162(h2,h3);
    L[0] = __nv_bfloat162(l0,l1); L[1] = __nv_bfloat162(l2,l3);
}

// ---------------- layernorm (optionally writing hi/lo bf16 split) ------------
template<bool SPLIT>
__global__ __launch_bounds__(256) void ln_kernel(
    const float* __restrict__ in, const float* __restrict__ w,
    const float* __restrict__ b, float* __restrict__ outf,
    bf16* __restrict__ outhi, bf16* __restrict__ outlo)
{
    int row = blockIdx.x;
    const float* x = in + (size_t)row * Dc;
    float s = 0.f, s2 = 0.f;
    for (int i = threadIdx.x; i < Dc; i += 256) {
        float v = x[i]; s += v; s2 += v * v;
    }
    __shared__ float r1[8], r2[8];
    s = warp_sum(s); s2 = warp_sum(s2);
    int wid = threadIdx.x >> 5, lane = threadIdx.x & 31;
    if (lane == 0) { r1[wid] = s; r2[wid] = s2; }
    __syncthreads();
    if (wid == 0) {
        s  = (lane < 8) ? r1[lane] : 0.f;
        s2 = (lane < 8) ? r2[lane] : 0.f;
        s = warp_sum(s); s2 = warp_sum(s2);
        if (lane == 0) { r1[0] = s; r2[0] = s2; }
    }
    __syncthreads();
    float mean = r1[0] * (1.0f / Dc);
    float var  = r2[0] * (1.0f / Dc) - mean * mean;
    float inv  = rsqrtf(var + LN_EPS);
    for (int i = threadIdx.x; i < Dc; i += 256) {
        float v = (x[i] - mean) * inv * w[i] + b[i];
        if (SPLIT) {
            bf16 hh, ll; split2(v, hh, ll);
            outhi[(size_t)row * Dc + i] = hh;
            outlo[(size_t)row * Dc + i] = ll;
        } else {
            outf[(size_t)row * Dc + i] = v;
        }
    }
}

// ---------------- MMA / ldmatrix helpers --------------------------------------
__device__ __forceinline__ void ldsm4(unsigned* r, unsigned addr) {
    asm volatile("ldmatrix.sync.aligned.m8n8.x4.shared.b16 {%0,%1,%2,%3},[%4];"
        : "=r"(r[0]), "=r"(r[1]), "=r"(r[2]), "=r"(r[3]) : "r"(addr));
}
__device__ __forceinline__ void ldsm4t(unsigned* r, unsigned addr) {
    asm volatile("ldmatrix.sync.aligned.m8n8.x4.trans.shared.b16 {%0,%1,%2,%3},[%4];"
        : "=r"(r[0]), "=r"(r[1]), "=r"(r[2]), "=r"(r[3]) : "r"(addr));
}
__device__ __forceinline__ void mma16816(float* c, const unsigned* a, const unsigned* b) {
    asm volatile("mma.sync.aligned.m16n8k16.row.col.f32.bf16.bf16.f32 "
        "{%0,%1,%2,%3},{%4,%5,%6,%7},{%8,%9},{%0,%1,%2,%3};"
        : "+f"(c[0]), "+f"(c[1]), "+f"(c[2]), "+f"(c[3])
        : "r"(a[0]), "r"(a[1]), "r"(a[2]), "r"(a[3]), "r"(b[0]), "r"(b[1]));
}
__device__ __forceinline__ void cp_async16(unsigned saddr, const void* g) {
    asm volatile("cp.async.cg.shared.global [%0], [%1], 16;" :: "r"(saddr), "l"(g));
}
__device__ __forceinline__ unsigned smem_u32(const void* p) {
    return (unsigned)__cvta_generic_to_shared(p);
}
__device__ __forceinline__ void packsplit(float x, float y, unsigned& hi, unsigned& lo) {
    bf16 hx = __float2bfloat16(x);
    bf16 hy = __float2bfloat16(y);
    bf16 lx = __float2bfloat16(x - __bfloat162float(hx));
    bf16 ly = __float2bfloat16(y - __bfloat162float(hy));
    __nv_bfloat162 H(hx, hy), L(lx, ly);
    hi = *(unsigned*)&H; lo = *(unsigned*)&L;
}

// ---------------- tensor-core GEMM (bf16x3 emulation of fp32) -----------------
// EPI 0: Cf = v+bias ; 1: Cf = res+v+bias ; 2: relu(v+bias)->split ; 3: (v+bias)->split
#define GBM 128
#define GBN 128
#define GBK 32
#define APAD 8
#define BPAD 8
#define ASTRIDE (GBK + APAD)
#define BSTRIDE (GBN + BPAD)
#define SA_ELEMS (2*2*GBM*ASTRIDE)
#define SB_ELEMS (2*2*GBK*BSTRIDE)
#define GSMEM_BYTES ((SA_ELEMS + SB_ELEMS) * 2)

template<int EPI>
__global__ void __launch_bounds__(256) gemm3_kernel(
    const bf16* __restrict__ Ahi, const bf16* __restrict__ Alo,
    const bf16* __restrict__ Bhi, const bf16* __restrict__ Blo,
    const float* __restrict__ bias, const float* __restrict__ res,
    float* __restrict__ Cf, bf16* __restrict__ Chi, bf16* __restrict__ Clo,
    int M, int N, int K)
{
    extern __shared__ __align__(16) bf16 smem[];
    bf16* sA = smem;
    bf16* sB = smem + SA_ELEMS;
    const int tid = threadIdx.x;
    const int lane = tid & 31, wid = tid >> 5;
    const int wm = wid & 3, wn = wid >> 2;
    const int bm = blockIdx.y * GBM, bn = blockIdx.x * GBN;

    unsigned sA_base = smem_u32(sA);
    unsigned sB_base = smem_u32(sB);

    float acc[2][8][4] = {};

    auto issue = [&](int it, int buf) {
        int k0 = it * GBK;
        #pragma unroll
        for (int j = 0; j < 4; j++) {
            int c = tid + j * 256;
            int p = c >> 9, rem = c & 511;
            int r = rem >> 2, kc = (rem & 3) << 3;
            const bf16* src = (p ? Alo : Ahi) + (size_t)(bm + r) * K + k0 + kc;
            unsigned dst = sA_base + (unsigned)(((buf*2 + p)*GBM + r)*ASTRIDE + kc) * 2u;
            cp_async16(dst, src);
        }
        #pragma unroll
        for (int j = 0; j < 4; j++) {
            int c = tid + j * 256;
            int p = c >> 9, rem = c & 511;
            int k = rem >> 4, nc = (rem & 15) << 3;
            const bf16* src = (p ? Blo : Bhi) + (size_t)(k0 + k) * N + bn + nc;
            unsigned dst = sB_base + (unsigned)(((buf*2 + p)*GBK + k)*BSTRIDE + nc) * 2u;
            cp_async16(dst, src);
        }
        asm volatile("cp.async.commit_group;" ::: "memory");
    };

    issue(0, 0);
    const int NIT = K >> 5;
    for (int it = 0; it < NIT; it++) {
        int buf = it & 1;
        if (it + 1 < NIT) {
            issue(it + 1, buf ^ 1);
            asm volatile("cp.async.wait_group 1;" ::: "memory");
        } else {
            asm volatile("cp.async.wait_group 0;" ::: "memory");
        }
        __syncthreads();
        #pragma unroll
        for (int ks = 0; ks < 2; ks++) {
            unsigned afrag[2][2][4];
            unsigned bfrag[2][8][2];
            int arow = wm * 32 + (lane & 15);
            int acol = ks * 16 + ((lane >> 4) << 3);
            #pragma unroll
            for (int mt = 0; mt < 2; mt++)
                #pragma unroll
                for (int p = 0; p < 2; p++)
                    ldsm4(afrag[mt][p],
                          sA_base + (unsigned)(((buf*2 + p)*GBM + arow + mt*16)*ASTRIDE + acol) * 2u);
            int brow = ks * 16 + (lane & 15);
            #pragma unroll
            for (int ng = 0; ng < 4; ng++) {
                int bcol = wn * 64 + ng * 16 + ((lane >> 4) << 3);
                #pragma unroll
                for (int p = 0; p < 2; p++) {
                    unsigned r4[4];
                    ldsm4t(r4, sB_base + (unsigned)(((buf*2 + p)*GBK + brow)*BSTRIDE + bcol) * 2u);
                    bfrag[p][2*ng][0]   = r4[0]; bfrag[p][2*ng][1]   = r4[1];
                    bfrag[p][2*ng+1][0] = r4[2]; bfrag[p][2*ng+1][1] = r4[3];
                }
            }
            #pragma unroll
            for (int mt = 0; mt < 2; mt++)
                #pragma unroll
                for (int nt = 0; nt < 8; nt++) {
                    mma16816(acc[mt][nt], afrag[mt][0], bfrag[0][nt]);
                    mma16816(acc[mt][nt], afrag[mt][0], bfrag[1][nt]);
                    mma16816(acc[mt][nt], afrag[mt][1], bfrag[0][nt]);
                }
        }
        __syncthreads();
    }

    #pragma unroll
    for (int mt = 0; mt < 2; mt++) {
        #pragma unroll
        for (int nt = 0; nt < 8; nt++) {
            int r0 = bm + wm * 32 + mt * 16 + (lane >> 2);
            int c0 = bn + wn * 64 + nt * 8 + ((lane & 3) << 1);
            #pragma unroll
            for (int hh = 0; hh < 2; hh++) {
                int rr = r0 + hh * 8;
                #pragma unroll
                for (int cc = 0; cc < 2; cc++) {
                    int col = c0 + cc;
                    float v = acc[mt][nt][hh*2 + cc] + bias[col];
                    size_t idx = (size_t)rr * N + col;
                    if (EPI == 0) {
                        Cf[idx] = v;
                    } else if (EPI == 1) {
                        Cf[idx] = res[idx] + v;
                    } else {
                        if (EPI == 2) v = fmaxf(v, 0.f);
                        bf16 vh, vl; split2(v, vh, vl);
                        Chi[idx] = vh; Clo[idx] = vl;
                    }
                }
            }
        }
    }
}

// ---------------- HMMA flash attention (bf16x3) -------------------------------
// block: 128 q-rows, 8 warps (16 q-rows each); k-tiles of 64 keys.
#define AQ 128
#define AKT 64
#define QSTR 72   // bf16 elems per smem row (64 + 8 pad)
#define ASMEM_BYTES (2*128*QSTR*2 + 4*64*QSTR*2 + 256)

__global__ void __launch_bounds__(256, 1) attn_mma_kernel(
    const bf16* __restrict__ qkv_hi, const bf16* __restrict__ qkv_lo,
    const float* __restrict__ amask,
    bf16* __restrict__ ctxhi, bf16* __restrict__ ctxlo)
{
    extern __shared__ __align__(16) char asmem[];
    bf16* sQh = (bf16*)asmem;
    bf16* sQl = sQh + 128*QSTR;
    bf16* sKh = sQl + 128*QSTR;
    bf16* sKl = sKh + 64*QSTR;
    bf16* sVh = sKl + 64*QSTR;
    bf16* sVl = sVh + 64*QSTR;
    float* skm = (float*)(sVl + 64*QSTR);

    const int tid = threadIdx.x, lane = tid & 31, w = tid >> 5;
    const int bh = blockIdx.y, b = bh >> 4, hh = bh & 15;
    const int q0 = blockIdx.x * AQ;
    const float scale = 0.125f;   // 1/sqrt(64)

    const size_t rstr = 3 * Dc;
    const bf16* qh = qkv_hi + (size_t)b * Tc * rstr + hh * HD;
    const bf16* ql = qkv_lo + (size_t)b * Tc * rstr + hh * HD;
    const bf16* kh = qh + Dc;  const bf16* kl = ql + Dc;
    const bf16* vh = qh + 2*Dc; const bf16* vl = ql + 2*Dc;

    // load Q tile (hi/lo): 2048 16B chunks
    #pragma unroll
    for (int j = 0; j < 8; j++) {
        int c = tid + j * 256;
        int p = c >> 10, rem = c & 1023;
        int row = rem >> 3, ch = rem & 7;
        *(uint4*)((p ? sQl : sQh) + row * QSTR + ch * 8) =
            *(const uint4*)((p ? ql : qh) + (size_t)(q0 + row) * rstr + ch * 8);
    }
    __syncthreads();

    const unsigned qb_h = smem_u32(sQh), qb_l = smem_u32(sQl);
    const unsigned kb_h = smem_u32(sKh), kb_l = smem_u32(sKl);
    const unsigned vb_h = smem_u32(sVh), vb_l = smem_u32(sVl);

    // Q a-fragments (fixed for whole block): [m16][k16] x 4 ksteps x hi/lo
    unsigned aQh[4][4], aQl[4][4];
    {
        int arow = w * 16 + (lane & 15);
        #pragma unroll
        for (int g = 0; g < 4; g++) {
            int acol = g * 16 + ((lane >> 4) << 3);
            unsigned off = (unsigned)(arow * QSTR + acol) * 2u;
            ldsm4(aQh[g], qb_h + off);
            ldsm4(aQl[g], qb_l + off);
        }
    }

    float acc[8][4];
    #pragma unroll
    for (int nt = 0; nt < 8; nt++)
        #pragma unroll
        for (int e = 0; e < 4; e++) acc[nt][e] = 0.f;
    float m0 = -1e30f, m1 = -1e30f, l0 = 0.f, l1 = 0.f;

    const int qg0 = q0 + w * 16 + (lane >> 2);
    const int ncol = (lane & 3) << 1;
    // K b-frag lane->address mapping (non-trans ldsm over [n][k] rows)
    const int kn_l = (lane & 7) + ((lane >> 4) << 3);
    const int kkoff = ((lane >> 3) & 1) << 3;

    const int nkt = 2 * blockIdx.x + 2;
    for (int kt = 0; kt < nkt; kt++) {
        int kk0 = kt * AKT;
        __syncthreads();
        #pragma unroll
        for (int j = 0; j < 8; j++) {
            int c = tid + j * 256;
            int arr = c >> 9, rem = c & 511;
            int row = rem >> 3, ch = rem & 7;
            const bf16* gp = (arr == 0) ? kh : (arr == 1) ? kl : (arr == 2) ? vh : vl;
            bf16* sp = (arr == 0) ? sKh : (arr == 1) ? sKl : (arr == 2) ? sVh : sVl;
            *(uint4*)(sp + row * QSTR + ch * 8) =
                *(const uint4*)(gp + (size_t)(kk0 + row) * rstr + ch * 8);
        }
        if (tid < 64) skm[tid] = (1.0f - amask[b * Tc + kk0 + tid]) * MASK_BIAS;
        __syncthreads();

        // ---- S = Q K^T (bf16x3) ----
        float S[8][4];
        #pragma unroll
        for (int nt = 0; nt < 8; nt++)
            #pragma unroll
            for (int e = 0; e < 4; e++) S[nt][e] = 0.f;

        #pragma unroll
        for (int g = 0; g < 4; g++) {
            unsigned bKh[8][2], bKl[8][2];
            #pragma unroll
            for (int np = 0; np < 4; np++) {
                unsigned off = (unsigned)((np * 16 + kn_l) * QSTR + g * 16 + kkoff) * 2u;
                unsigned r4[4];
                ldsm4(r4, kb_h + off);
                bKh[2*np][0] = r4[0]; bKh[2*np][1] = r4[1];
                bKh[2*np+1][0] = r4[2]; bKh[2*np+1][1] = r4[3];
                ldsm4(r4, kb_l + off);
                bKl[2*np][0] = r4[0]; bKl[2*np][1] = r4[1];
                bKl[2*np+1][0] = r4[2]; bKl[2*np+1][1] = r4[3];
            }
            #pragma unroll
            for (int nt = 0; nt < 8; nt++) {
                mma16816(S[nt], aQh[g], bKh[nt]);
                mma16816(S[nt], aQh[g], bKl[nt]);
                mma16816(S[nt], aQl[g], bKh[nt]);
            }
        }

        // ---- scale + causal + mask ----
        float tmax0 = -1e30f, tmax1 = -1e30f;
        #pragma unroll
        for (int nt = 0; nt < 8; nt++) {
            int n0 = kk0 + nt * 8 + ncol;
            float km0 = skm[nt * 8 + ncol], km1 = skm[nt * 8 + ncol + 1];
            float s0 = (n0     <= qg0    ) ? S[nt][0] * scale + km0 : -1e30f;
            float s1 = (n0 + 1 <= qg0    ) ? S[nt][1] * scale + km1 : -1e30f;
            float s2 = (n0     <= qg0 + 8) ? S[nt][2] * scale + km0 : -1e30f;
            float s3 = (n0 + 1 <= qg0 + 8) ? S[nt][3] * scale + km1 : -1e30f;
            S[nt][0] = s0; S[nt][1] = s1; S[nt][2] = s2; S[nt][3] = s3;
            tmax0 = fmaxf(tmax0, fmaxf(s0, s1));
            tmax1 = fmaxf(tmax1, fmaxf(s2, s3));
        }
        tmax0 = fmaxf(tmax0, __shfl_xor_sync(0xffffffffu, tmax0, 1));
        tmax0 = fmaxf(tmax0, __shfl_xor_sync(0xffffffffu, tmax0, 2));
        tmax1 = fmaxf(tmax1, __shfl_xor_sync(0xffffffffu, tmax1, 1));
        tmax1 = fmaxf(tmax1, __shfl_xor_sync(0xffffffffu, tmax1, 2));

        float nm0 = fmaxf(m0, tmax0), nm1 = fmaxf(m1, tmax1);
        float cr0 = __expf(m0 - nm0), cr1 = __expf(m1 - nm1);
        m0 = nm0; m1 = nm1;

        float sum0 = 0.f, sum1 = 0.f;
        #pragma unroll
        for (int nt = 0; nt < 8; nt++) {
            float p0 = __expf(S[nt][0] - m0);
            float p1 = __expf(S[nt][1] - m0);
            float p2 = __expf(S[nt][2] - m1);
            float p3 = __expf(S[nt][3] - m1);
            S[nt][0] = p0; S[nt][1] = p1; S[nt][2] = p2; S[nt][3] = p3;
            sum0 += p0 + p1; sum1 += p2 + p3;
        }
        sum0 += __shfl_xor_sync(0xffffffffu, sum0, 1);
        sum0 += __shfl_xor_sync(0xffffffffu, sum0, 2);
        sum1 += __shfl_xor_sync(0xffffffffu, sum1, 1);
        sum1 += __shfl_xor_sync(0xffffffffu, sum1, 2);
        l0 = l0 * cr0 + sum0;
        l1 = l1 * cr1 + sum1;
        #pragma unroll
        for (int nt = 0; nt < 8; nt++) {
            acc[nt][0] *= cr0; acc[nt][1] *= cr0;
            acc[nt][2] *= cr1; acc[nt][3] *= cr1;
        }

        // ---- acc += P V (bf16x3) ----
        #pragma unroll
        for (int g = 0; g < 4; g++) {
            unsigned aPh[4], aPl[4];
            packsplit(S[2*g][0],   S[2*g][1],   aPh[0], aPl[0]);
            packsplit(S[2*g][2],   S[2*g][3],   aPh[1], aPl[1]);
            packsplit(S[2*g+1][0], S[2*g+1][1], aPh[2], aPl[2]);
            packsplit(S[2*g+1][2], S[2*g+1][3], aPh[3], aPl[3]);
            unsigned bVh[8][2], bVl[8][2];
            int brow = g * 16 + (lane & 15);
            #pragma unroll
            for (int np = 0; np < 4; np++) {
                int bcol = np * 16 + ((lane >> 4) << 3);
                unsigned off = (unsigned)(brow * QSTR + bcol) * 2u;
                unsigned r4[4];
                ldsm4t(r4, vb_h + off);
                bVh[2*np][0] = r4[0]; bVh[2*np][1] = r4[1];
                bVh[2*np+1][0] = r4[2]; bVh[2*np+1][1] = r4[3];
                ldsm4t(r4, vb_l + off);
                bVl[2*np][0] = r4[0]; bVl[2*np][1] = r4[1];
                bVl[2*np+1][0] = r4[2]; bVl[2*np+1][1] = r4[3];
            }
            #pragma unroll
            for (int nt = 0; nt < 8; nt++) {
                mma16816(acc[nt], aPh, bVh[nt]);
                mma16816(acc[nt], aPh, bVl[nt]);
                mma16816(acc[nt], aPl, bVh[nt]);
            }
        }
    }

    // ---- epilogue: ctx = acc / l -> hi/lo split ----
    float il0 = 1.0f / l0, il1 = 1.0f / l1;
    int row0 = q0 + w * 16 + (lane >> 2);
    size_t o0 = ((size_t)(b * Tc + row0)) * Dc + hh * HD + ncol;
    size_t o1 = ((size_t)(b * Tc + row0 + 8)) * Dc + hh * HD + ncol;
    #pragma unroll
    for (int nt = 0; nt < 8; nt++) {
        float v0 = acc[nt][0] * il0, v1 = acc[nt][1] * il0;
        float v2 = acc[nt][2] * il1, v3 = acc[nt][3] * il1;
        bf16 h0,lo0,h1,lo1,h2,lo2,h3,lo3;
        split2(v0,h0,lo0); split2(v1,h1,lo1); split2(v2,h2,lo2); split2(v3,h3,lo3);
        *(__nv_bfloat162*)(ctxhi + o0 + nt*8) = __nv_bfloat162(h0, h1);
        *(__nv_bfloat162*)(ctxlo + o0 + nt*8) = __nv_bfloat162(lo0, lo1);
        *(__nv_bfloat162*)(ctxhi + o1 + nt*8) = __nv_bfloat162(h2, h3);
        *(__nv_bfloat162*)(ctxlo + o1 + nt*8) = __nv_bfloat162(lo2, lo3);
    }
}

// ---------------- launch -----------------------------------------------------
extern "C" void kernel_launch(void* const* d_in, const int* in_sizes, int n_in,
                              void* d_out, int out_size)
{
    const float* emb    = (const float*)d_in[0];
    const float* amask  = (const float*)d_in[1];
    const float* ln1_w  = (const float*)d_in[2];
    const float* ln1_b  = (const float*)d_in[3];
    const float* attn_w = (const float*)d_in[4];
    const float* attn_b = (const float*)d_in[5];
    const float* proj_w = (const float*)d_in[6];
    const float* proj_b = (const float*)d_in[7];
    const float* ln2_w  = (const float*)d_in[8];
    const float* ln2_b  = (const float*)d_in[9];
    const float* fc_w   = (const float*)d_in[10];
    const float* fc_b   = (const float*)d_in[11];
    const float* fcp_w  = (const float*)d_in[12];
    const float* fcp_b  = (const float*)d_in[13];
    const float* lnf_w  = (const float*)d_in[14];
    const float* lnf_b  = (const float*)d_in[15];
    float* out = (float*)d_out;

    float* h;
    bf16 *qhi, *qlo, *xhi, *xlo, *chi, *clo, *ahi, *alo;
    bf16 *wq_h, *wq_l, *wp_h, *wp_l, *wf_h, *wf_l, *wg_h, *wg_l;
    cudaGetSymbolAddress((void**)&h,    g_h);
    cudaGetSymbolAddress((void**)&qhi,  g_qhi);  cudaGetSymbolAddress((void**)&qlo, g_qlo);
    cudaGetSymbolAddress((void**)&xhi,  g_xhi);  cudaGetSymbolAddress((void**)&xlo, g_xlo);
    cudaGetSymbolAddress((void**)&chi,  g_chi);  cudaGetSymbolAddress((void**)&clo, g_clo);
    cudaGetSymbolAddress((void**)&ahi,  g_ahi);  cudaGetSymbolAddress((void**)&alo, g_alo);
    cudaGetSymbolAddress((void**)&wq_h, g_wqkv_hi); cudaGetSymbolAddress((void**)&wq_l, g_wqkv_lo);
    cudaGetSymbolAddress((void**)&wp_h, g_wprj_hi); cudaGetSymbolAddress((void**)&wp_l, g_wprj_lo);
    cudaGetSymbolAddress((void**)&wf_h, g_wfc_hi);  cudaGetSymbolAddress((void**)&wf_l, g_wfc_lo);
    cudaGetSymbolAddress((void**)&wg_h, g_wfp_hi);  cudaGetSymbolAddress((void**)&wg_l, g_wfp_lo);

    cudaFuncSetAttribute(gemm3_kernel<0>, cudaFuncAttributeMaxDynamicSharedMemorySize, GSMEM_BYTES);
    cudaFuncSetAttribute(gemm3_kernel<1>, cudaFuncAttributeMaxDynamicSharedMemorySize, GSMEM_BYTES);
    cudaFuncSetAttribute(gemm3_kernel<2>, cudaFuncAttributeMaxDynamicSharedMemorySize, GSMEM_BYTES);
    cudaFuncSetAttribute(gemm3_kernel<3>, cudaFuncAttributeMaxDynamicSharedMemorySize, GSMEM_BYTES);
    cudaFuncSetAttribute(attn_mma_kernel, cudaFuncAttributeMaxDynamicSharedMemorySize, ASMEM_BYTES);

    // weight splits [K,N] hi/lo
    { int n4 = Lc*Dc*3*Dc/4; split4_kernel<<<(n4+255)/256, 256>>>(attn_w, wq_h, wq_l, n4); }
    { int n4 = Lc*Dc*Dc/4;   split4_kernel<<<(n4+255)/256, 256>>>(proj_w, wp_h, wp_l, n4); }
    { int n4 = Lc*Dc*Ic/4;   split4_kernel<<<(n4+255)/256, 256>>>(fc_w,   wf_h, wf_l, n4); }
    { int n4 = Lc*Ic*Dc/4;   split4_kernel<<<(n4+255)/256, 256>>>(fcp_w,  wg_h, wg_l, n4); }

    // h = inputs_embeds
    { int n = ROWS * Dc; copy_kernel<<<(n + 255) / 256, 256>>>(emb, h, n); }

    for (int l = 0; l < Lc; l++) {
        // x = ln1(h) -> split
        ln_kernel<true><<<ROWS, 256>>>(h, ln1_w + (size_t)l*Dc, ln1_b + (size_t)l*Dc,
                                       nullptr, xhi, xlo);
        // qkv = x @ attn_w + attn_b  -> bf16 hi/lo
        gemm3_kernel<3><<<dim3(3*Dc/GBN, ROWS/GBM), 256, GSMEM_BYTES>>>(
            xhi, xlo, wq_h + (size_t)l*Dc*3*Dc, wq_l + (size_t)l*Dc*3*Dc,
            attn_b + (size_t)l*3*Dc, nullptr, nullptr, qhi, qlo,
            ROWS, 3*Dc, Dc);
        // ctx = attention(qkv) -> split
        attn_mma_kernel<<<dim3(Tc/AQ, Bc*Hc), 256, ASMEM_BYTES>>>(qhi, qlo, amask, chi, clo);
        // h = h + ctx @ proj_w + proj_b
        gemm3_kernel<1><<<dim3(Dc/GBN, ROWS/GBM), 256, GSMEM_BYTES>>>(
            chi, clo, wp_h + (size_t)l*Dc*Dc, wp_l + (size_t)l*Dc*Dc,
            proj_b + (size_t)l*Dc, h, h, nullptr, nullptr,
            ROWS, Dc, Dc);
        // x = ln2(h) -> split
        ln_kernel<true><<<ROWS, 256>>>(h, ln2_w + (size_t)l*Dc, ln2_b + (size_t)l*Dc,
                                       nullptr, xhi, xlo);
        // act = relu(x @ fc_w + fc_b) -> split
        gemm3_kernel<2><<<dim3(Ic/GBN, ROWS/GBM), 256, GSMEM_BYTES>>>(
            xhi, xlo, wf_h + (size_t)l*Dc*Ic, wf_l + (size_t)l*Dc*Ic,
            fc_b + (size_t)l*Ic, nullptr, nullptr, ahi, alo,
            ROWS, Ic, Dc);
        // h = h + act @ fcp_w + fcp_b
        gemm3_kernel<1><<<dim3(Dc/GBN, ROWS/GBM), 256, GSMEM_BYTES>>>(
            ahi, alo, wg_h + (size_t)l*Ic*Dc, wg_l + (size_t)l*Ic*Dc,
            fcp_b + (size_t)l*Dc, h, h, nullptr, nullptr,
            ROWS, Dc, Ic);
    }
    // out = ln_f(h) (fp32)
    ln_kernel<false><<<ROWS, 256>>>(h, lnf_w, lnf_b, out, nullptr, nullptr);
}

// round 10
// speedup vs baseline: 5.6927x; 1.0375x over previous
#include <cuda_runtime.h>
#include <cuda_bf16.h>
#include <math.h>
#include <stdint.h>

// Problem constants
#define Bc 2
#define Tc 2048
#define Dc 1024
#define Hc 16
#define Lc 8
#define Ic 4096
#define HD 64
#define ROWS (Bc*Tc)    // 4096 token rows
#define LN_EPS 1e-5f
#define MASK_BIAS -10000.0f

typedef __nv_bfloat16 bf16;

// ---------------- scratch (static device globals; no allocation) -------------
__device__ float g_h[ROWS * Dc];            // residual stream (fp32)
__device__ bf16  g_qhi[ROWS * 3 * Dc], g_qlo[ROWS * 3 * Dc];  // qkv split
__device__ bf16  g_xhi[ROWS * Dc],  g_xlo[ROWS * Dc];     // LN output split
__device__ bf16  g_chi[ROWS * Dc],  g_clo[ROWS * Dc];     // attention ctx split
__device__ bf16  g_ahi[ROWS * Ic],  g_alo[ROWS * Ic];     // ffn inner split
// weight splits [K, N] layout
__device__ bf16 g_wqkv_hi[Lc*Dc*3*Dc], g_wqkv_lo[Lc*Dc*3*Dc];
__device__ bf16 g_wprj_hi[Lc*Dc*Dc],   g_wprj_lo[Lc*Dc*Dc];
__device__ bf16 g_wfc_hi [Lc*Dc*Ic],   g_wfc_lo [Lc*Dc*Ic];
__device__ bf16 g_wfp_hi [Lc*Ic*Dc],   g_wfp_lo [Lc*Ic*Dc];

// ---------------- utility ----------------------------------------------------
__inline__ __device__ float warp_sum(float v) {
    #pragma unroll
    for (int o = 16; o > 0; o >>= 1) v += __shfl_xor_sync(0xffffffffu, v, o);
    return v;
}
__device__ __forceinline__ void split2(float v, bf16& hi, bf16& lo) {
    hi = __float2bfloat16(v);
    lo = __float2bfloat16(v - __bfloat162float(hi));
}

// ---------------- copy / weight split ----------------------------------------
__global__ void copy_kernel(const float* __restrict__ src, float* __restrict__ dst, int n) {
    int i = blockIdx.x * blockDim.x + threadIdx.x;
    if (i < n) dst[i] = src[i];
}

__global__ void split4_kernel(const float* __restrict__ src,
                              bf16* __restrict__ hi, bf16* __restrict__ lo, int n4) {
    int i = blockIdx.x * blockDim.x + threadIdx.x;
    if (i >= n4) return;
    float4 v = ((const float4*)src)[i];
    bf16 h0,l0,h1,l1,h2,l2,h3,l3;
    split2(v.x,h0,l0); split2(v.y,h1,l1); split2(v.z,h2,l2); split2(v.w,h3,l3);
    __nv_bfloat162* H = (__nv_bfloat162*)(hi + 4*(size_t)i);
    __nv_bfloat162* L = (__nv_bfloat162*)(lo + 4*(size_t)i);
    H[0] = __nv_bfloat162(h0,h1); H[1] = __nv_bfloat162(h2,h3);
    L[0] = __nv_bfloat162(l0,l1); L[1] = __nv_bfloat162(l2,l3);
}

// ---------------- layernorm (optionally writing hi/lo bf16 split) ------------
template<bool SPLIT>
__global__ __launch_bounds__(256) void ln_kernel(
    const float* __restrict__ in, const float* __restrict__ w,
    const float* __restrict__ b, float* __restrict__ outf,
    bf16* __restrict__ outhi, bf16* __restrict__ outlo)
{
    int row = blockIdx.x;
    const float* x = in + (size_t)row * Dc;
    float s = 0.f, s2 = 0.f;
    for (int i = threadIdx.x; i < Dc; i += 256) {
        float v = x[i]; s += v; s2 += v * v;
    }
    __shared__ float r1[8], r2[8];
    s = warp_sum(s); s2 = warp_sum(s2);
    int wid = threadIdx.x >> 5, lane = threadIdx.x & 31;
    if (lane == 0) { r1[wid] = s; r2[wid] = s2; }
    __syncthreads();
    if (wid == 0) {
        s  = (lane < 8) ? r1[lane] : 0.f;
        s2 = (lane < 8) ? r2[lane] : 0.f;
        s = warp_sum(s); s2 = warp_sum(s2);
        if (lane == 0) { r1[0] = s; r2[0] = s2; }
    }
    __syncthreads();
    float mean = r1[0] * (1.0f / Dc);
    float var  = r2[0] * (1.0f / Dc) - mean * mean;
    float inv  = rsqrtf(var + LN_EPS);
    for (int i = threadIdx.x; i < Dc; i += 256) {
        float v = (x[i] - mean) * inv * w[i] + b[i];
        if (SPLIT) {
            bf16 hh, ll; split2(v, hh, ll);
            outhi[(size_t)row * Dc + i] = hh;
            outlo[(size_t)row * Dc + i] = ll;
        } else {
            outf[(size_t)row * Dc + i] = v;
        }
    }
}

// ---------------- MMA / ldmatrix helpers --------------------------------------
__device__ __forceinline__ void ldsm4(unsigned* r, unsigned addr) {
    asm volatile("ldmatrix.sync.aligned.m8n8.x4.shared.b16 {%0,%1,%2,%3},[%4];"
        : "=r"(r[0]), "=r"(r[1]), "=r"(r[2]), "=r"(r[3]) : "r"(addr));
}
__device__ __forceinline__ void ldsm4t(unsigned* r, unsigned addr) {
    asm volatile("ldmatrix.sync.aligned.m8n8.x4.trans.shared.b16 {%0,%1,%2,%3},[%4];"
        : "=r"(r[0]), "=r"(r[1]), "=r"(r[2]), "=r"(r[3]) : "r"(addr));
}
__device__ __forceinline__ void mma16816(float* c, const unsigned* a, const unsigned* b) {
    asm volatile("mma.sync.aligned.m16n8k16.row.col.f32.bf16.bf16.f32 "
        "{%0,%1,%2,%3},{%4,%5,%6,%7},{%8,%9},{%0,%1,%2,%3};"
        : "+f"(c[0]), "+f"(c[1]), "+f"(c[2]), "+f"(c[3])
        : "r"(a[0]), "r"(a[1]), "r"(a[2]), "r"(a[3]), "r"(b[0]), "r"(b[1]));
}
__device__ __forceinline__ void cp_async16(unsigned saddr, const void* g) {
    asm volatile("cp.async.cg.shared.global [%0], [%1], 16;" :: "r"(saddr), "l"(g));
}
__device__ __forceinline__ unsigned smem_u32(const void* p) {
    return (unsigned)__cvta_generic_to_shared(p);
}
__device__ __forceinline__ void packsplit(float x, float y, unsigned& hi, unsigned& lo) {
    bf16 hx = __float2bfloat16(x);
    bf16 hy = __float2bfloat16(y);
    bf16 lx = __float2bfloat16(x - __bfloat162float(hx));
    bf16 ly = __float2bfloat16(y - __bfloat162float(hy));
    __nv_bfloat162 H(hx, hy), L(lx, ly);
    hi = *(unsigned*)&H; lo = *(unsigned*)&L;
}

// ---------------- tensor-core GEMM (bf16x3 emulation of fp32) -----------------
// EPI 0: Cf = v+bias ; 1: Cf = res+v+bias ; 2: relu(v+bias)->split ; 3: (v+bias)->split
// A tiles: padded rows (ASTRIDE). B tiles: 256B rows with XOR-swizzled 16B chunks
// (chunk ^= row&7) -> conflict-free ldsm4t without padding; smem fits 2 CTAs/SM.
#define GBM 128
#define GBN 128
#define GBK 32
#define APAD 8
#define ASTRIDE (GBK + APAD)          // 40 elems (80B rows)
#define SA_ELEMS (2*2*GBM*ASTRIDE)    // 40960 bf16 = 81920 B
#define SB_BYTES_TILE (GBK * 256)     // 8192 B per (buf,p) tile
#define SB_BYTES (2*2*SB_BYTES_TILE)  // 32768 B
#define GSMEM_BYTES (SA_ELEMS*2 + SB_BYTES)   // 114688 B

template<int EPI>
__global__ void __launch_bounds__(256, 2) gemm3_kernel(
    const bf16* __restrict__ Ahi, const bf16* __restrict__ Alo,
    const bf16* __restrict__ Bhi, const bf16* __restrict__ Blo,
    const float* __restrict__ bias, const float* __restrict__ res,
    float* __restrict__ Cf, bf16* __restrict__ Chi, bf16* __restrict__ Clo,
    int M, int N, int K)
{
    extern __shared__ __align__(16) bf16 smem[];
    bf16* sA = smem;
    char* sB = (char*)(smem + SA_ELEMS);
    const int tid = threadIdx.x;
    const int lane = tid & 31, wid = tid >> 5;
    const int wm = wid & 3, wn = wid >> 2;
    const int bm = blockIdx.y * GBM, bn = blockIdx.x * GBN;

    unsigned sA_base = smem_u32(sA);
    unsigned sB_base = smem_u32(sB);

    float acc[2][8][4] = {};

    auto issue = [&](int it, int buf) {
        int k0 = it * GBK;
        #pragma unroll
        for (int j = 0; j < 4; j++) {
            int c = tid + j * 256;
            int p = c >> 9, rem = c & 511;
            int r = rem >> 2, kc = (rem & 3) << 3;
            const bf16* src = (p ? Alo : Ahi) + (size_t)(bm + r) * K + k0 + kc;
            unsigned dst = sA_base + (unsigned)(((buf*2 + p)*GBM + r)*ASTRIDE + kc) * 2u;
            cp_async16(dst, src);
        }
        #pragma unroll
        for (int j = 0; j < 4; j++) {
            int c = tid + j * 256;
            int p = c >> 9, rem = c & 511;
            int k = rem >> 4, nc = rem & 15;            // row k, 16B chunk nc
            const bf16* src = (p ? Blo : Bhi) + (size_t)(k0 + k) * N + bn + nc * 8;
            unsigned dst = sB_base + (unsigned)((buf*2 + p) * SB_BYTES_TILE
                          + k * 256 + ((nc ^ (k & 7)) << 4));
            cp_async16(dst, src);
        }
        asm volatile("cp.async.commit_group;" ::: "memory");
    };

    issue(0, 0);
    const int NIT = K >> 5;
    for (int it = 0; it < NIT; it++) {
        int buf = it & 1;
        if (it + 1 < NIT) {
            issue(it + 1, buf ^ 1);
            asm volatile("cp.async.wait_group 1;" ::: "memory");
        } else {
            asm volatile("cp.async.wait_group 0;" ::: "memory");
        }
        __syncthreads();
        #pragma unroll
        for (int ks = 0; ks < 2; ks++) {
            unsigned afrag[2][2][4];
            int arow = wm * 32 + (lane & 15);
            int acol = ks * 16 + ((lane >> 4) << 3);
            #pragma unroll
            for (int mt = 0; mt < 2; mt++)
                #pragma unroll
                for (int p = 0; p < 2; p++)
                    ldsm4(afrag[mt][p],
                          sA_base + (unsigned)(((buf*2 + p)*GBM + arow + mt*16)*ASTRIDE + acol) * 2u);
            int brow = ks * 16 + (lane & 15);
            unsigned brow_off = (unsigned)(brow * 256 + (((brow & 7) ) << 4));  // XOR base for chunk 0
            // process B in two half-tiles of 4 nt each to cut live registers
            #pragma unroll
            for (int half = 0; half < 2; half++) {
                unsigned bfrag[2][4][2];
                #pragma unroll
                for (int ngh = 0; ngh < 2; ngh++) {
                    int ng = half * 2 + ngh;
                    int chunk = wn * 8 + ng * 2 + (lane >> 4);   // 16B chunk index
                    #pragma unroll
                    for (int p = 0; p < 2; p++) {
                        unsigned addr = sB_base + (unsigned)((buf*2 + p) * SB_BYTES_TILE
                                      + brow * 256 + ((chunk ^ (brow & 7)) << 4));
                        unsigned r4[4];
                        ldsm4t(r4, addr);
                        bfrag[p][2*ngh][0]   = r4[0]; bfrag[p][2*ngh][1]   = r4[1];
                        bfrag[p][2*ngh+1][0] = r4[2]; bfrag[p][2*ngh+1][1] = r4[3];
                    }
                }
                #pragma unroll
                for (int mt = 0; mt < 2; mt++)
                    #pragma unroll
                    for (int nt = 0; nt < 4; nt++) {
                        float* a = acc[mt][half*4 + nt];
                        mma16816(a, afrag[mt][0], bfrag[0][nt]);
                        mma16816(a, afrag[mt][0], bfrag[1][nt]);
                        mma16816(a, afrag[mt][1], bfrag[0][nt]);
                    }
            }
        }
        __syncthreads();
    }

    #pragma unroll
    for (int mt = 0; mt < 2; mt++) {
        #pragma unroll
        for (int nt = 0; nt < 8; nt++) {
            int r0 = bm + wm * 32 + mt * 16 + (lane >> 2);
            int c0 = bn + wn * 64 + nt * 8 + ((lane & 3) << 1);
            #pragma unroll
            for (int hh = 0; hh < 2; hh++) {
                int rr = r0 + hh * 8;
                #pragma unroll
                for (int cc = 0; cc < 2; cc++) {
                    int col = c0 + cc;
                    float v = acc[mt][nt][hh*2 + cc] + bias[col];
                    size_t idx = (size_t)rr * N + col;
                    if (EPI == 0) {
                        Cf[idx] = v;
                    } else if (EPI == 1) {
                        Cf[idx] = res[idx] + v;
                    } else {
                        if (EPI == 2) v = fmaxf(v, 0.f);
                        bf16 vh, vl; split2(v, vh, vl);
                        Chi[idx] = vh; Clo[idx] = vl;
                    }
                }
            }
        }
    }
}

// ---------------- HMMA flash attention (bf16x3) -------------------------------
// block: 128 q-rows, 8 warps (16 q-rows each); k-tiles of 64 keys.
#define AQ 128
#define AKT 64
#define QSTR 72   // bf16 elems per smem row (64 + 8 pad)
#define ASMEM_BYTES (2*128*QSTR*2 + 4*64*QSTR*2 + 256)

__global__ void __launch_bounds__(256, 1) attn_mma_kernel(
    const bf16* __restrict__ qkv_hi, const bf16* __restrict__ qkv_lo,
    const float* __restrict__ amask,
    bf16* __restrict__ ctxhi, bf16* __restrict__ ctxlo)
{
    extern __shared__ __align__(16) char asmem[];
    bf16* sQh = (bf16*)asmem;
    bf16* sQl = sQh + 128*QSTR;
    bf16* sKh = sQl + 128*QSTR;
    bf16* sKl = sKh + 64*QSTR;
    bf16* sVh = sKl + 64*QSTR;
    bf16* sVl = sVh + 64*QSTR;
    float* skm = (float*)(sVl + 64*QSTR);

    const int tid = threadIdx.x, lane = tid & 31, w = tid >> 5;
    const int bh = blockIdx.y, b = bh >> 4, hh = bh & 15;
    const int q0 = blockIdx.x * AQ;
    const float scale = 0.125f;   // 1/sqrt(64)

    const size_t rstr = 3 * Dc;
    const bf16* qh = qkv_hi + (size_t)b * Tc * rstr + hh * HD;
    const bf16* ql = qkv_lo + (size_t)b * Tc * rstr + hh * HD;
    const bf16* kh = qh + Dc;  const bf16* kl = ql + Dc;
    const bf16* vh = qh + 2*Dc; const bf16* vl = ql + 2*Dc;

    #pragma unroll
    for (int j = 0; j < 8; j++) {
        int c = tid + j * 256;
        int p = c >> 10, rem = c & 1023;
        int row = rem >> 3, ch = rem & 7;
        *(uint4*)((p ? sQl : sQh) + row * QSTR + ch * 8) =
            *(const uint4*)((p ? ql : qh) + (size_t)(q0 + row) * rstr + ch * 8);
    }
    __syncthreads();

    const unsigned qb_h = smem_u32(sQh), qb_l = smem_u32(sQl);
    const unsigned kb_h = smem_u32(sKh), kb_l = smem_u32(sKl);
    const unsigned vb_h = smem_u32(sVh), vb_l = smem_u32(sVl);

    unsigned aQh[4][4], aQl[4][4];
    {
        int arow = w * 16 + (lane & 15);
        #pragma unroll
        for (int g = 0; g < 4; g++) {
            int acol = g * 16 + ((lane >> 4) << 3);
            unsigned off = (unsigned)(arow * QSTR + acol) * 2u;
            ldsm4(aQh[g], qb_h + off);
            ldsm4(aQl[g], qb_l + off);
        }
    }

    float acc[8][4];
    #pragma unroll
    for (int nt = 0; nt < 8; nt++)
        #pragma unroll
        for (int e = 0; e < 4; e++) acc[nt][e] = 0.f;
    float m0 = -1e30f, m1 = -1e30f, l0 = 0.f, l1 = 0.f;

    const int qg0 = q0 + w * 16 + (lane >> 2);
    const int ncol = (lane & 3) << 1;
    const int kn_l = (lane & 7) + ((lane >> 4) << 3);
    const int kkoff = ((lane >> 3) & 1) << 3;

    const int nkt = 2 * blockIdx.x + 2;
    for (int kt = 0; kt < nkt; kt++) {
        int kk0 = kt * AKT;
        __syncthreads();
        #pragma unroll
        for (int j = 0; j < 8; j++) {
            int c = tid + j * 256;
            int arr = c >> 9, rem = c & 511;
            int row = rem >> 3, ch = rem & 7;
            const bf16* gp = (arr == 0) ? kh : (arr == 1) ? kl : (arr == 2) ? vh : vl;
            bf16* sp = (arr == 0) ? sKh : (arr == 1) ? sKl : (arr == 2) ? sVh : sVl;
            *(uint4*)(sp + row * QSTR + ch * 8) =
                *(const uint4*)(gp + (size_t)(kk0 + row) * rstr + ch * 8);
        }
        if (tid < 64) skm[tid] = (1.0f - amask[b * Tc + kk0 + tid]) * MASK_BIAS;
        __syncthreads();

        float S[8][4];
        #pragma unroll
        for (int nt = 0; nt < 8; nt++)
            #pragma unroll
            for (int e = 0; e < 4; e++) S[nt][e] = 0.f;

        #pragma unroll
        for (int g = 0; g < 4; g++) {
            unsigned bKh[8][2], bKl[8][2];
            #pragma unroll
            for (int np = 0; np < 4; np++) {
                unsigned off = (unsigned)((np * 16 + kn_l) * QSTR + g * 16 + kkoff) * 2u;
                unsigned r4[4];
                ldsm4(r4, kb_h + off);
                bKh[2*np][0] = r4[0]; bKh[2*np][1] = r4[1];
                bKh[2*np+1][0] = r4[2]; bKh[2*np+1][1] = r4[3];
                ldsm4(r4, kb_l + off);
                bKl[2*np][0] = r4[0]; bKl[2*np][1] = r4[1];
                bKl[2*np+1][0] = r4[2]; bKl[2*np+1][1] = r4[3];
            }
            #pragma unroll
            for (int nt = 0; nt < 8; nt++) {
                mma16816(S[nt], aQh[g], bKh[nt]);
                mma16816(S[nt], aQh[g], bKl[nt]);
                mma16816(S[nt], aQl[g], bKh[nt]);
            }
        }

        float tmax0 = -1e30f, tmax1 = -1e30f;
        #pragma unroll
        for (int nt = 0; nt < 8; nt++) {
            int n0 = kk0 + nt * 8 + ncol;
            float km0 = skm[nt * 8 + ncol], km1 = skm[nt * 8 + ncol + 1];
            float s0 = (n0     <= qg0    ) ? S[nt][0] * scale + km0 : -1e30f;
            float s1 = (n0 + 1 <= qg0    ) ? S[nt][1] * scale + km1 : -1e30f;
            float s2 = (n0     <= qg0 + 8) ? S[nt][2] * scale + km0 : -1e30f;
            float s3 = (n0 + 1 <= qg0 + 8) ? S[nt][3] * scale + km1 : -1e30f;
            S[nt][0] = s0; S[nt][1] = s1; S[nt][2] = s2; S[nt][3] = s3;
            tmax0 = fmaxf(tmax0, fmaxf(s0, s1));
            tmax1 = fmaxf(tmax1, fmaxf(s2, s3));
        }
        tmax0 = fmaxf(tmax0, __shfl_xor_sync(0xffffffffu, tmax0, 1));
        tmax0 = fmaxf(tmax0, __shfl_xor_sync(0xffffffffu, tmax0, 2));
        tmax1 = fmaxf(tmax1, __shfl_xor_sync(0xffffffffu, tmax1, 1));
        tmax1 = fmaxf(tmax1, __shfl_xor_sync(0xffffffffu, tmax1, 2));

        float nm0 = fmaxf(m0, tmax0), nm1 = fmaxf(m1, tmax1);
        float cr0 = __expf(m0 - nm0), cr1 = __expf(m1 - nm1);
        m0 = nm0; m1 = nm1;

        float sum0 = 0.f, sum1 = 0.f;
        #pragma unroll
        for (int nt = 0; nt < 8; nt++) {
            float p0 = __expf(S[nt][0] - m0);
            float p1 = __expf(S[nt][1] - m0);
            float p2 = __expf(S[nt][2] - m1);
            float p3 = __expf(S[nt][3] - m1);
            S[nt][0] = p0; S[nt][1] = p1; S[nt][2] = p2; S[nt][3] = p3;
            sum0 += p0 + p1; sum1 += p2 + p3;
        }
        sum0 += __shfl_xor_sync(0xffffffffu, sum0, 1);
        sum0 += __shfl_xor_sync(0xffffffffu, sum0, 2);
        sum1 += __shfl_xor_sync(0xffffffffu, sum1, 1);
        sum1 += __shfl_xor_sync(0xffffffffu, sum1, 2);
        l0 = l0 * cr0 + sum0;
        l1 = l1 * cr1 + sum1;
        #pragma unroll
        for (int nt = 0; nt < 8; nt++) {
            acc[nt][0] *= cr0; acc[nt][1] *= cr0;
            acc[nt][2] *= cr1; acc[nt][3] *= cr1;
        }

        #pragma unroll
        for (int g = 0; g < 4; g++) {
            unsigned aPh[4], aPl[4];
            packsplit(S[2*g][0],   S[2*g][1],   aPh[0], aPl[0]);
            packsplit(S[2*g][2],   S[2*g][3],   aPh[1], aPl[1]);
            packsplit(S[2*g+1][0], S[2*g+1][1], aPh[2], aPl[2]);
            packsplit(S[2*g+1][2], S[2*g+1][3], aPh[3], aPl[3]);
            unsigned bVh[8][2], bVl[8][2];
            int brow = g * 16 + (lane & 15);
            #pragma unroll
            for (int np = 0; np < 4; np++) {
                int bcol = np * 16 + ((lane >> 4) << 3);
                unsigned off = (unsigned)(brow * QSTR + bcol) * 2u;
                unsigned r4[4];
                ldsm4t(r4, vb_h + off);
                bVh[2*np][0] = r4[0]; bVh[2*np][1] = r4[1];
                bVh[2*np+1][0] = r4[2]; bVh[2*np+1][1] = r4[3];
                ldsm4t(r4, vb_l + off);
                bVl[2*np][0] = r4[0]; bVl[2*np][1] = r4[1];
                bVl[2*np+1][0] = r4[2]; bVl[2*np+1][1] = r4[3];
            }
            #pragma unroll
            for (int nt = 0; nt < 8; nt++) {
                mma16816(acc[nt], aPh, bVh[nt]);
                mma16816(acc[nt], aPh, bVl[nt]);
                mma16816(acc[nt], aPl, bVh[nt]);
            }
        }
    }

    float il0 = 1.0f / l0, il1 = 1.0f / l1;
    int row0 = q0 + w * 16 + (lane >> 2);
    size_t o0 = ((size_t)(b * Tc + row0)) * Dc + hh * HD + ncol;
    size_t o1 = ((size_t)(b * Tc + row0 + 8)) * Dc + hh * HD + ncol;
    #pragma unroll
    for (int nt = 0; nt < 8; nt++) {
        float v0 = acc[nt][0] * il0, v1 = acc[nt][1] * il0;
        float v2 = acc[nt][2] * il1, v3 = acc[nt][3] * il1;
        bf16 h0,lo0,h1,lo1,h2,lo2,h3,lo3;
        split2(v0,h0,lo0); split2(v1,h1,lo1); split2(v2,h2,lo2); split2(v3,h3,lo3);
        *(__nv_bfloat162*)(ctxhi + o0 + nt*8) = __nv_bfloat162(h0, h1);
        *(__nv_bfloat162*)(ctxlo + o0 + nt*8) = __nv_bfloat162(lo0, lo1);
        *(__nv_bfloat162*)(ctxhi + o1 + nt*8) = __nv_bfloat162(h2, h3);
        *(__nv_bfloat162*)(ctxlo + o1 + nt*8) = __nv_bfloat162(lo2, lo3);
    }
}

// ---------------- launch -----------------------------------------------------
extern "C" void kernel_launch(void* const* d_in, const int* in_sizes, int n_in,
                              void* d_out, int out_size)
{
    const float* emb    = (const float*)d_in[0];
    const float* amask  = (const float*)d_in[1];
    const float* ln1_w  = (const float*)d_in[2];
    const float* ln1_b  = (const float*)d_in[3];
    const float* attn_w = (const float*)d_in[4];
    const float* attn_b = (const float*)d_in[5];
    const float* proj_w = (const float*)d_in[6];
    const float* proj_b = (const float*)d_in[7];
    const float* ln2_w  = (const float*)d_in[8];
    const float* ln2_b  = (const float*)d_in[9];
    const float* fc_w   = (const float*)d_in[10];
    const float* fc_b   = (const float*)d_in[11];
    const float* fcp_w  = (const float*)d_in[12];
    const float* fcp_b  = (const float*)d_in[13];
    const float* lnf_w  = (const float*)d_in[14];
    const float* lnf_b  = (const float*)d_in[15];
    float* out = (float*)d_out;

    float* h;
    bf16 *qhi, *qlo, *xhi, *xlo, *chi, *clo, *ahi, *alo;
    bf16 *wq_h, *wq_l, *wp_h, *wp_l, *wf_h, *wf_l, *wg_h, *wg_l;
    cudaGetSymbolAddress((void**)&h,    g_h);
    cudaGetSymbolAddress((void**)&qhi,  g_qhi);  cudaGetSymbolAddress((void**)&qlo, g_qlo);
    cudaGetSymbolAddress((void**)&xhi,  g_xhi);  cudaGetSymbolAddress((void**)&xlo, g_xlo);
    cudaGetSymbolAddress((void**)&chi,  g_chi);  cudaGetSymbolAddress((void**)&clo, g_clo);
    cudaGetSymbolAddress((void**)&ahi,  g_ahi);  cudaGetSymbolAddress((void**)&alo, g_alo);
    cudaGetSymbolAddress((void**)&wq_h, g_wqkv_hi); cudaGetSymbolAddress((void**)&wq_l, g_wqkv_lo);
    cudaGetSymbolAddress((void**)&wp_h, g_wprj_hi); cudaGetSymbolAddress((void**)&wp_l, g_wprj_lo);
    cudaGetSymbolAddress((void**)&wf_h, g_wfc_hi);  cudaGetSymbolAddress((void**)&wf_l, g_wfc_lo);
    cudaGetSymbolAddress((void**)&wg_h, g_wfp_hi);  cudaGetSymbolAddress((void**)&wg_l, g_wfp_lo);

    cudaFuncSetAttribute(gemm3_kernel<0>, cudaFuncAttributeMaxDynamicSharedMemorySize, GSMEM_BYTES);
    cudaFuncSetAttribute(gemm3_kernel<1>, cudaFuncAttributeMaxDynamicSharedMemorySize, GSMEM_BYTES);
    cudaFuncSetAttribute(gemm3_kernel<2>, cudaFuncAttributeMaxDynamicSharedMemorySize, GSMEM_BYTES);
    cudaFuncSetAttribute(gemm3_kernel<3>, cudaFuncAttributeMaxDynamicSharedMemorySize, GSMEM_BYTES);
    cudaFuncSetAttribute(attn_mma_kernel, cudaFuncAttributeMaxDynamicSharedMemorySize, ASMEM_BYTES);

    // weight splits [K,N] hi/lo
    { int n4 = Lc*Dc*3*Dc/4; split4_kernel<<<(n4+255)/256, 256>>>(attn_w, wq_h, wq_l, n4); }
    { int n4 = Lc*Dc*Dc/4;   split4_kernel<<<(n4+255)/256, 256>>>(proj_w, wp_h, wp_l, n4); }
    { int n4 = Lc*Dc*Ic/4;   split4_kernel<<<(n4+255)/256, 256>>>(fc_w,   wf_h, wf_l, n4); }
    { int n4 = Lc*Ic*Dc/4;   split4_kernel<<<(n4+255)/256, 256>>>(fcp_w,  wg_h, wg_l, n4); }

    // h = inputs_embeds
    { int n = ROWS * Dc; copy_kernel<<<(n + 255) / 256, 256>>>(emb, h, n); }

    for (int l = 0; l < Lc; l++) {
        // x = ln1(h) -> split
        ln_kernel<true><<<ROWS, 256>>>(h, ln1_w + (size_t)l*Dc, ln1_b + (size_t)l*Dc,
                                       nullptr, xhi, xlo);
        // qkv = x @ attn_w + attn_b  -> bf16 hi/lo
        gemm3_kernel<3><<<dim3(3*Dc/GBN, ROWS/GBM), 256, GSMEM_BYTES>>>(
            xhi, xlo, wq_h + (size_t)l*Dc*3*Dc, wq_l + (size_t)l*Dc*3*Dc,
            attn_b + (size_t)l*3*Dc, nullptr, nullptr, qhi, qlo,
            ROWS, 3*Dc, Dc);
        // ctx = attention(qkv) -> split
        attn_mma_kernel<<<dim3(Tc/AQ, Bc*Hc), 256, ASMEM_BYTES>>>(qhi, qlo, amask, chi, clo);
        // h = h + ctx @ proj_w + proj_b
        gemm3_kernel<1><<<dim3(Dc/GBN, ROWS/GBM), 256, GSMEM_BYTES>>>(
            chi, clo, wp_h + (size_t)l*Dc*Dc, wp_l + (size_t)l*Dc*Dc,
            proj_b + (size_t)l*Dc, h, h, nullptr, nullptr,
            ROWS, Dc, Dc);
        // x = ln2(h) -> split
        ln_kernel<true><<<ROWS, 256>>>(h, ln2_w + (size_t)l*Dc, ln2_b + (size_t)l*Dc,
                                       nullptr, xhi, xlo);
        // act = relu(x @ fc_w + fc_b) -> split
        gemm3_kernel<2><<<dim3(Ic/GBN, ROWS/GBM), 256, GSMEM_BYTES>>>(
            xhi, xlo, wf_h + (size_t)l*Dc*Ic, wf_l + (size_t)l*Dc*Ic,
            fc_b + (size_t)l*Ic, nullptr, nullptr, ahi, alo,
            ROWS, Ic, Dc);
        // h = h + act @ fcp_w + fcp_b
        gemm3_kernel<1><<<dim3(Dc/GBN, ROWS/GBM), 256, GSMEM_BYTES>>>(
            ahi, alo, wg_h + (size_t)l*Ic*Dc, wg_l + (size_t)l*Ic*Dc,
            fcp_b + (size_t)l*Dc, h, h, nullptr, nullptr,
            ROWS, Dc, Ic);
    }
    // out = ln_f(h) (fp32)
    ln_kernel<false><<<ROWS, 256>>>(h, lnf_w, lnf_b, out, nullptr, nullptr);
}